// round 15
// baseline (speedup 1.0000x reference)
#include <cuda_runtime.h>
#include <cuda_fp16.h>
#include <math.h>
#include <stdint.h>
#include <stddef.h>

typedef unsigned long long u64;

#define NB   100
#define TT   512
#define IND  256
#define HD   1024
#define H3   3072
#define NDB  (HD * NB)          // 102400
#define HBT_STRIDE (128 * 1024) // padded per-t stride (128 batch rows x 1024)
#define HFRAGU_T 28672          // uint32 per t in fp16 fragment layout (8*7*8*32*4)

// ---------------- scratch ----------------
__device__ float    g_xp [(size_t)TT * NB * H3];    // xp [t][b][g]; later reused as S [u][j]
__device__ float    g_hbt[(size_t)TT * HBT_STRIDE]; // h states [t][b(pad128)][k] fp32
__device__ unsigned g_hfrag[(size_t)TT * HFRAGU_T]; // h states, fp16 mma A-fragment layout
__device__ float g_v  [NB * HD];
__device__ float g_hp [NB * HD];
__device__ float g_inner[NB * HD];
__device__ float g_catv[5 * HD];
__device__ float g_hp2 [5 * HD];
__device__ float g_cat [5 * HD];
__device__ float g_as[NB];
__device__ float g_ad[NB];
__device__ float g_as2[8];
__device__ float g_ad2[8];
__device__ float g_fin[NB * H3];
__device__ float g_f  [NB * HD];
__device__ unsigned g_grpcnt[16 * 32];  // group counters, 128B apart
__device__ unsigned g_mcnt;
__device__ unsigned g_gen;

// ---------------- helpers ----------------
__device__ __forceinline__ u64 bcast2(float x) {
    u64 r; unsigned u = __float_as_uint(x);
    asm("mov.b64 %0, {%1, %1};" : "=l"(r) : "r"(u));
    return r;
}
__device__ __forceinline__ void fma2(u64& d, u64 a, u64 b) {
    asm("fma.rn.f32x2 %0, %1, %2, %0;" : "+l"(d) : "l"(a), "l"(b));
}
__device__ __forceinline__ float2 unpk(u64 v) {
    unsigned lo, hi;
    asm("mov.b64 {%0, %1}, %2;" : "=r"(lo), "=r"(hi) : "l"(v));
    return make_float2(__uint_as_float(lo), __uint_as_float(hi));
}
__device__ __forceinline__ uint32_t f2tf32(float x) {
    uint32_t u;
    asm("cvt.rna.tf32.f32 %0, %1;" : "=r"(u) : "f"(x));
    return u;
}
__device__ __forceinline__ uint32_t packh2(float lo, float hi) {
    __half2 h = __floats2half2_rn(lo, hi);
    return *(uint32_t*)&h;
}
__device__ __forceinline__ float fsig(float x) {
    return __fdividef(1.f, 1.f + __expf(-x));
}
__device__ __forceinline__ float ftanh(float x) {
    float ax = fabsf(x);
    float e = __expf(2.f * ax);
    float t = 1.f - __fdividef(2.f, e + 1.f);
    return copysignf(t, x);
}

// tf32 warp MMA: D(16x8) += A(16x8) * B(8x8)
__device__ __forceinline__ void mma_tf32(
    float& c0, float& c1, float& c2, float& c3,
    uint32_t a0, uint32_t a1, uint32_t a2, uint32_t a3,
    uint32_t b0, uint32_t b1)
{
    asm volatile(
        "mma.sync.aligned.m16n8k8.row.col.f32.tf32.tf32.f32 "
        "{%0,%1,%2,%3}, {%4,%5,%6,%7}, {%8,%9}, {%0,%1,%2,%3};"
        : "+f"(c0), "+f"(c1), "+f"(c2), "+f"(c3)
        : "r"(a0), "r"(a1), "r"(a2), "r"(a3), "r"(b0), "r"(b1));
}
// fp16 warp MMA: D(16x8) += A(16x16) * B(16x8), fp32 accumulate
__device__ __forceinline__ void mma_f16(
    float& c0, float& c1, float& c2, float& c3,
    uint32_t a0, uint32_t a1, uint32_t a2, uint32_t a3,
    uint32_t b0, uint32_t b1)
{
    asm volatile(
        "mma.sync.aligned.m16n8k16.row.col.f32.f16.f16.f32 "
        "{%0,%1,%2,%3}, {%4,%5,%6,%7}, {%8,%9}, {%0,%1,%2,%3};"
        : "+f"(c0), "+f"(c1), "+f"(c2), "+f"(c3)
        : "r"(a0), "r"(a1), "r"(a2), "r"(a3), "r"(b0), "r"(b1));
}

// =================================================================
// tf32 tensor-core GEMM NT (remap: xp stored as [t][b][g])
// =================================================================
#define AST 36
__global__ __launch_bounds__(256) void gemm_nt_tc(
    const float* __restrict__ A, const float* __restrict__ B,
    const float* __restrict__ colbias, float* __restrict__ C,
    int M, int N, int K, int act, int remap)
{
    __shared__ uint32_t As[128 * AST];
    __shared__ uint32_t Bs[128 * AST];
    int tid = threadIdx.x, w = tid >> 5, lane = tid & 31;
    int gid = lane >> 2, tig = lane & 3;
    int wm = w >> 2, wn = w & 3;
    int row0 = blockIdx.y * 128, col0 = blockIdx.x * 128;

    float acc[4][4][4];
#pragma unroll
    for (int i = 0; i < 4; i++)
#pragma unroll
        for (int j = 0; j < 4; j++)
#pragma unroll
            for (int q = 0; q < 4; q++) acc[i][j][q] = 0.f;

    for (int k0 = 0; k0 < K; k0 += 32) {
#pragma unroll
        for (int q = 0; q < 4; q++) {
            int idx = tid + q * 256;
            int row = idx >> 3, k4 = (idx & 7) * 4;
            float4 v = *(const float4*)(A + (size_t)(row0 + row) * K + k0 + k4);
            uint32_t* d = &As[row * AST + k4];
            d[0] = f2tf32(v.x); d[1] = f2tf32(v.y); d[2] = f2tf32(v.z); d[3] = f2tf32(v.w);
        }
#pragma unroll
        for (int q = 0; q < 4; q++) {
            int idx = tid + q * 256;
            int row = idx >> 3, k4 = (idx & 7) * 4;
            float4 v = *(const float4*)(B + (size_t)(col0 + row) * K + k0 + k4);
            uint32_t* d = &Bs[row * AST + k4];
            d[0] = f2tf32(v.x); d[1] = f2tf32(v.y); d[2] = f2tf32(v.z); d[3] = f2tf32(v.w);
        }
        __syncthreads();
#pragma unroll
        for (int kq = 0; kq < 4; kq++) {
            int kb = kq * 8;
            uint32_t af[4][4];
#pragma unroll
            for (int i = 0; i < 4; i++) {
                int base = (wm * 64 + i * 16 + gid) * AST + kb + tig;
                af[i][0] = As[base];
                af[i][1] = As[base + 8 * AST];
                af[i][2] = As[base + 4];
                af[i][3] = As[base + 8 * AST + 4];
            }
#pragma unroll
            for (int j = 0; j < 4; j++) {
                int bbase = (wn * 32 + j * 8 + gid) * AST + kb + tig;
                uint32_t b0 = Bs[bbase], b1 = Bs[bbase + 4];
#pragma unroll
                for (int i = 0; i < 4; i++)
                    mma_tf32(acc[i][j][0], acc[i][j][1], acc[i][j][2], acc[i][j][3],
                             af[i][0], af[i][1], af[i][2], af[i][3], b0, b1);
            }
        }
        __syncthreads();
    }
#pragma unroll
    for (int i = 0; i < 4; i++) {
#pragma unroll
        for (int j = 0; j < 4; j++) {
            int r = row0 + wm * 64 + i * 16 + gid;
            int r2 = r + 8;
            int cix = col0 + wn * 32 + j * 8 + tig * 2;
            float v0 = acc[i][j][0], v1 = acc[i][j][1];
            float v2 = acc[i][j][2], v3 = acc[i][j][3];
            if (colbias) {
                float bb0 = colbias[cix], bb1 = colbias[cix + 1];
                v0 += bb0; v1 += bb1; v2 += bb0; v3 += bb1;
            }
            if (act == 1) {
                v0 = fmaxf(v0, 0.f); v1 = fmaxf(v1, 0.f);
                v2 = fmaxf(v2, 0.f); v3 = fmaxf(v3, 0.f);
            }
            size_t ro = (size_t)r, ro2 = (size_t)r2;
            if (remap) {
                ro  = (size_t)(r  % TT) * NB + (r  / TT);
                ro2 = (size_t)(r2 % TT) * NB + (r2 / TT);
            }
            C[ro  * N + cix]     = v0;
            C[ro  * N + cix + 1] = v1;
            C[ro2 * N + cix]     = v2;
            C[ro2 * N + cix + 1] = v3;
        }
    }
}

// =================================================================
// tf32 tensor-core GEMM NN: C[M,N] = A[M,K] @ B[K(ldB),N] + rowbias[M]
// =================================================================
#define BSTN 132
__global__ __launch_bounds__(256) void gemm_nn_tc(
    const float* __restrict__ A, const float* __restrict__ B,
    const float* __restrict__ rowbias, float* __restrict__ C,
    int M, int N, int K, size_t ldB)
{
    __shared__ uint32_t As[128 * AST];
    __shared__ uint32_t Bs[32 * BSTN];
    int tid = threadIdx.x, w = tid >> 5, lane = tid & 31;
    int gid = lane >> 2, tig = lane & 3;
    int wm = w >> 2, wn = w & 3;
    int row0 = blockIdx.y * 128, col0 = blockIdx.x * 128;

    float acc[4][4][4];
#pragma unroll
    for (int i = 0; i < 4; i++)
#pragma unroll
        for (int j = 0; j < 4; j++)
#pragma unroll
            for (int q = 0; q < 4; q++) acc[i][j][q] = 0.f;

    for (int k0 = 0; k0 < K; k0 += 32) {
#pragma unroll
        for (int q = 0; q < 4; q++) {
            int idx = tid + q * 256;
            int row = idx >> 3, k4 = (idx & 7) * 4;
            float4 v = *(const float4*)(A + (size_t)(row0 + row) * K + k0 + k4);
            uint32_t* d = &As[row * AST + k4];
            d[0] = f2tf32(v.x); d[1] = f2tf32(v.y); d[2] = f2tf32(v.z); d[3] = f2tf32(v.w);
        }
#pragma unroll
        for (int q = 0; q < 4; q++) {
            int idx = tid + q * 256;
            int k = idx >> 5, n4 = (idx & 31) * 4;
            float4 v = *(const float4*)(B + (size_t)(k0 + k) * ldB + col0 + n4);
            uint32_t* d = &Bs[k * BSTN + n4];
            d[0] = f2tf32(v.x); d[1] = f2tf32(v.y); d[2] = f2tf32(v.z); d[3] = f2tf32(v.w);
        }
        __syncthreads();
#pragma unroll
        for (int kq = 0; kq < 4; kq++) {
            int kb = kq * 8;
            uint32_t af[4][4];
#pragma unroll
            for (int i = 0; i < 4; i++) {
                int base = (wm * 64 + i * 16 + gid) * AST + kb + tig;
                af[i][0] = As[base];
                af[i][1] = As[base + 8 * AST];
                af[i][2] = As[base + 4];
                af[i][3] = As[base + 8 * AST + 4];
            }
#pragma unroll
            for (int j = 0; j < 4; j++) {
                int ncol = wn * 32 + j * 8 + gid;
                uint32_t b0 = Bs[(kb + tig) * BSTN + ncol];
                uint32_t b1 = Bs[(kb + tig + 4) * BSTN + ncol];
#pragma unroll
                for (int i = 0; i < 4; i++)
                    mma_tf32(acc[i][j][0], acc[i][j][1], acc[i][j][2], acc[i][j][3],
                             af[i][0], af[i][1], af[i][2], af[i][3], b0, b1);
            }
        }
        __syncthreads();
    }
#pragma unroll
    for (int i = 0; i < 4; i++) {
#pragma unroll
        for (int j = 0; j < 4; j++) {
            int r = row0 + wm * 64 + i * 16 + gid;
            int cix = col0 + wn * 32 + j * 8 + tig * 2;
            float rb0 = rowbias ? rowbias[r] : 0.f;
            float rb8 = rowbias ? rowbias[r + 8] : 0.f;
            C[(size_t)r * N + cix]           = acc[i][j][0] + rb0;
            C[(size_t)r * N + cix + 1]       = acc[i][j][1] + rb0;
            C[(size_t)(r + 8) * N + cix]     = acc[i][j][2] + rb8;
            C[(size_t)(r + 8) * N + cix + 1] = acc[i][j][3] + rb8;
        }
    }
}

// =================================================================
// SIMT SGEMM NT (small GEMMs)
// =================================================================
__global__ __launch_bounds__(256) void gemm_nt(
    const float* __restrict__ A, const float* __restrict__ B,
    const float* __restrict__ colbias, float* __restrict__ C,
    int M, int N, int K, int act)
{
    __shared__ float As[16][128];
    __shared__ float Bs[16][128];
    int tid = threadIdx.x;
    int tx = tid & 15, ty = tid >> 4;
    int row0 = blockIdx.y * 128, col0 = blockIdx.x * 128;

    u64 acc[8][4];
#pragma unroll
    for (int i = 0; i < 8; i++)
#pragma unroll
        for (int j = 0; j < 4; j++) acc[i][j] = 0ull;

    int lr = tid >> 2, lc = tid & 3;
    for (int k0 = 0; k0 < K; k0 += 16) {
#pragma unroll
        for (int p = 0; p < 2; p++) {
            int r = lr + p * 64, gr = row0 + r;
            float4 v = make_float4(0.f, 0.f, 0.f, 0.f);
            if (gr < M) v = *(const float4*)(A + (size_t)gr * K + k0 + lc * 4);
            As[lc*4+0][r] = v.x; As[lc*4+1][r] = v.y; As[lc*4+2][r] = v.z; As[lc*4+3][r] = v.w;
        }
#pragma unroll
        for (int p = 0; p < 2; p++) {
            int r = lr + p * 64, gc = col0 + r;
            float4 v = make_float4(0.f, 0.f, 0.f, 0.f);
            if (gc < N) v = *(const float4*)(B + (size_t)gc * K + k0 + lc * 4);
            Bs[lc*4+0][r] = v.x; Bs[lc*4+1][r] = v.y; Bs[lc*4+2][r] = v.z; Bs[lc*4+3][r] = v.w;
        }
        __syncthreads();
#pragma unroll
        for (int kk = 0; kk < 16; kk++) {
            float a[8];
            *(float4*)&a[0] = *(const float4*)&As[kk][ty * 8];
            *(float4*)&a[4] = *(const float4*)&As[kk][ty * 8 + 4];
            u64 b4[4];
#pragma unroll
            for (int j = 0; j < 4; j++) b4[j] = *(const u64*)&Bs[kk][tx * 8 + 2 * j];
#pragma unroll
            for (int i = 0; i < 8; i++) {
                u64 ai = bcast2(a[i]);
#pragma unroll
                for (int j = 0; j < 4; j++) fma2(acc[i][j], ai, b4[j]);
            }
        }
        __syncthreads();
    }
#pragma unroll
    for (int i = 0; i < 8; i++) {
        int gm = row0 + ty * 8 + i;
        if (gm >= M) continue;
#pragma unroll
        for (int j = 0; j < 4; j++) {
            float2 c2 = unpk(acc[i][j]);
            int gn = col0 + tx * 8 + 2 * j;
            float v0 = c2.x, v1 = c2.y;
            if (colbias) { v0 += colbias[gn]; v1 += colbias[gn + 1]; }
            if (act == 1) { v0 = fmaxf(v0, 0.f); v1 = fmaxf(v1, 0.f); }
            if (gn < N)     C[(size_t)gm * N + gn]     = v0;
            if (gn + 1 < N) C[(size_t)gm * N + gn + 1] = v1;
        }
    }
}

// =================================================================
// Persistent GRU v15: fp16 mma + prefetch + reg-hold + tree barrier.
// pbuf layout [w][row(112)][n(24)]; float2 partial stores.
// =================================================================
#define PBW 2688                  // 112*24
#define PBUF_F (8 * PBW)
#define GRU_SMEM (PBUF_F * 4)     // 86016

__device__ __forceinline__ void gridbar_tree()
{
    __threadfence();
    __syncthreads();
    if (threadIdx.x == 0) {
        volatile unsigned* vg = &g_gen;
        unsigned target = *vg + 1;
        int grp = blockIdx.x >> 3;            // 16 groups of 8
        unsigned v = atomicAdd(&g_grpcnt[grp * 32], 1) + 1;
        if ((v & 7) == 0) {                   // 8th arrival in group
            unsigned m = atomicAdd(&g_mcnt, 1) + 1;
            if ((m & 15) == 0) {              // 16th group
                __threadfence();
                atomicAdd(&g_gen, 1);
            }
        }
        while ((int)(*vg - target) < 0) { }
        __threadfence();
    }
    __syncthreads();
}

__global__ __launch_bounds__(256, 1) void gru_mma(
    const float* __restrict__ xpt, const float* __restrict__ Whh,
    const float* __restrict__ bhh, float* __restrict__ hbt,
    unsigned* __restrict__ hfragu)
{
    extern __shared__ float pbuf[];   // [8][112][24]
    int tid  = threadIdx.x;
    int w    = tid >> 5;
    int lane = tid & 31;
    int gidq = lane >> 2;
    int tig  = lane & 3;
    int col0 = blockIdx.x * 8;
    int k0   = w * 128;

    // register-resident Whh fragments (fp16, 48 regs)
    uint32_t bf[8][3][2];
#pragma unroll
    for (int kt = 0; kt < 8; kt++) {
#pragma unroll
        for (int j = 0; j < 3; j++) {
            int n = j * 8 + gidq;
            int c = n / 3, g = n % 3;
            const float* wrow = Whh + ((size_t)g * HD + col0 + c) * HD;
            int kb = k0 + kt * 16 + 2 * tig;
            bf[kt][j][0] = packh2(wrow[kb],     wrow[kb + 1]);
            bf[kt][j][1] = packh2(wrow[kb + 8], wrow[kb + 9]);
        }
    }

    float* pw = pbuf + w * PBW;
    float holdr[4] = { 0.f, 0.f, 0.f, 0.f };

    for (int t = 0; t < TT; t++) {
        if (t > 0) {
            const uint4* fb = (const uint4*)(hfragu + (size_t)(t - 1) * HFRAGU_T)
                              + (size_t)w * 7 * 8 * 32 + lane;
            uint4 acur[8];
#pragma unroll
            for (int kt = 0; kt < 8; kt++) acur[kt] = fb[(size_t)kt * 32];

#pragma unroll 1
            for (int mt = 0; mt < 7; mt++) {
                uint4 anxt[8];
                if (mt < 6) {
                    const uint4* fn = fb + (size_t)((mt + 1) * 8) * 32;
#pragma unroll
                    for (int kt = 0; kt < 8; kt++) anxt[kt] = fn[(size_t)kt * 32];
                }

                float c0[3], c1[3], c2[3], c3[3];
#pragma unroll
                for (int j = 0; j < 3; j++) { c0[j] = 0.f; c1[j] = 0.f; c2[j] = 0.f; c3[j] = 0.f; }
#pragma unroll
                for (int kt = 0; kt < 8; kt++) {
                    uint4 a = acur[kt];
#pragma unroll
                    for (int j = 0; j < 3; j++)
                        mma_f16(c0[j], c1[j], c2[j], c3[j],
                                a.x, a.y, a.z, a.w, bf[kt][j][0], bf[kt][j][1]);
                }

                int r0 = mt * 16 + gidq;
#pragma unroll
                for (int j = 0; j < 3; j++) {
                    int n0 = j * 8 + tig * 2;
                    *(float2*)(pw + (size_t)r0 * 24 + n0)       = make_float2(c0[j], c1[j]);
                    *(float2*)(pw + (size_t)(r0 + 8) * 24 + n0) = make_float2(c2[j], c3[j]);
                }
#pragma unroll
                for (int kt = 0; kt < 8; kt++) acur[kt] = anxt[kt];
            }
        }
        __syncthreads();

        // fused reduction + gate epilogue (static idx->(b,c); hold in regs)
        __half* hf = (__half*)(hfragu + (size_t)t * HFRAGU_T);
#pragma unroll
        for (int q = 0; q < 4; q++) {
            int idx = tid + q * 256;
            if (idx < NB * 8) {
                int b = idx >> 3, c = idx & 7;
                int col = col0 + c;
                float ar = 0.f, az = 0.f, an = 0.f;
                if (t > 0) {
                    const float* pr = pbuf + (size_t)b * 24 + c * 3;
#pragma unroll
                    for (int ww = 0; ww < 8; ww++) {
                        ar += pr[ww * PBW];
                        az += pr[ww * PBW + 1];
                        an += pr[ww * PBW + 2];
                    }
                }
                size_t xbase = ((size_t)t * NB + b) * H3;
                float xr = xpt[xbase + col];
                float xz = xpt[xbase + HD + col];
                float xn = xpt[xbase + 2 * HD + col];
                float r = fsig(xr + ar + bhh[col]);
                float z = fsig(xz + az + bhh[HD + col]);
                float n = ftanh(xn + r * (an + bhh[2 * HD + col]));
                float hnew = (1.f - z) * n + z * holdr[q];
                holdr[q] = hnew;

                hbt[(size_t)t * HBT_STRIDE + (size_t)b * HD + col] = hnew;

                // fp16 fragment-layout write
                int fw  = col >> 7;
                int kl  = col & 127;
                int fkt = kl >> 4;
                int kk  = kl & 15;
                int ah  = kk >> 3;
                int ktg = (kk & 7) >> 1;
                int hlf = kk & 1;
                int fgid = b & 7;
                int rh   = (b >> 3) & 1;
                int fmt  = b >> 4;
                size_t u32idx = ((((size_t)fw * 7 + fmt) * 8 + fkt) * 32 + fgid * 4 + ktg) * 4
                                + (rh + 2 * ah);
                hf[u32idx * 2 + hlf] = __float2half_rn(hnew);
            }
        }

        gridbar_tree();
    }
}

// =================================================================
// one-pass online-softmax reduce
// =================================================================
__global__ void att_reduce_flat(const float* __restrict__ S,
                                const float* __restrict__ H,
                                float* __restrict__ v)
{
    int j = blockIdx.x * 256 + threadIdx.x;
    float mx = -1e30f, se = 0.f, sv = 0.f;
#pragma unroll 4
    for (int u = 0; u < TT; u++) {
        float s = S[(size_t)u * NDB + j];
        float h = H[(size_t)u * HBT_STRIDE + j];
        float m2 = fmaxf(mx, s);
        float cor = __expf(mx - m2);
        float e = __expf(s - m2);
        se = se * cor + e;
        sv = sv * cor + e * h;
        mx = m2;
    }
    v[j] = __fdividef(sv, se);
}

// pool attention, row-major v -> catv[c][d]
__global__ void pool_att(const float* __restrict__ v, const float* __restrict__ pW,
                         const float* __restrict__ pb, float* __restrict__ catv)
{
    int c = blockIdx.x;
    int d = blockIdx.y * 256 + threadIdx.x;
    __shared__ float sW[400];
    __shared__ float sb[20];
    for (int i = threadIdx.x; i < 400; i += 256) sW[i] = pW[i];
    if (threadIdx.x < 20) sb[threadIdx.x] = pb[threadIdx.x];
    __syncthreads();

    float xv[20];
#pragma unroll
    for (int s = 0; s < 20; s++) xv[s] = v[(size_t)(c * 20 + s) * HD + d];
    float wv[20]; float mx = -1e30f;
#pragma unroll
    for (int u = 0; u < 20; u++) {
        float s = sb[u];
#pragma unroll
        for (int t2 = 0; t2 < 20; t2++) s += xv[t2] * sW[u * 20 + t2];
        wv[u] = s; mx = fmaxf(mx, s);
    }
    float se = 0.f, sv = 0.f;
#pragma unroll
    for (int u = 0; u < 20; u++) {
        float e = __expf(wv[u] - mx);
        se += e; sv += e * xv[u];
    }
    catv[(size_t)c * HD + d] = __fdividef(sv, se);
}

// two dots per node (row-major)
__global__ void dot2(const float* __restrict__ h, const float* __restrict__ a1,
                     const float* __restrict__ a2, float* __restrict__ o1,
                     float* __restrict__ o2)
{
    int n = blockIdx.x;
    __shared__ float s1[256], s2[256];
    float p1 = 0.f, p2 = 0.f;
    for (int k = threadIdx.x; k < HD; k += 256) {
        float hv = h[(size_t)n * HD + k];
        p1 += hv * a1[k]; p2 += hv * a2[k];
    }
    s1[threadIdx.x] = p1; s2[threadIdx.x] = p2;
    __syncthreads();
    for (int s = 128; s > 0; s >>= 1) {
        if (threadIdx.x < s) { s1[threadIdx.x] += s1[threadIdx.x + s]; s2[threadIdx.x] += s2[threadIdx.x + s]; }
        __syncthreads();
    }
    if (threadIdx.x == 0) { o1[n] = s1[0]; o2[n] = s2[0]; }
}

// GAT aggregation (complete cliques + self loops), row-major
__global__ void gat_agg(const float* __restrict__ h, const float* __restrict__ as,
                        const float* __restrict__ ad, const float* __restrict__ bias,
                        float* __restrict__ out, int group)
{
    int n = blockIdx.x;
    int base = (n / group) * group;
    __shared__ float alpha[32];
    if (threadIdx.x == 0) {
        float e[32]; float mx = -1e30f;
        for (int s = 0; s < group; s++) {
            float x = as[base + s] + ad[n];
            x = (x > 0.f) ? x : 0.2f * x;
            e[s] = x; mx = fmaxf(mx, x);
        }
        float se = 0.f;
        for (int s = 0; s < group; s++) { e[s] = __expf(e[s] - mx); se += e[s]; }
        for (int s = 0; s < group; s++) alpha[s] = __fdividef(e[s], se);
    }
    __syncthreads();
    for (int dd = threadIdx.x; dd < HD; dd += 256) {
        float acc = 0.f;
        for (int s = 0; s < group; s++)
            acc += alpha[s] * h[(size_t)(base + s) * HD + dd];
        out[(size_t)n * HD + dd] = acc + bias[dd];
    }
}

// fusion concat (row-major)
__global__ void build_fusion(const float* __restrict__ v, const float* __restrict__ catv,
                             const float* __restrict__ inner, float* __restrict__ fin)
{
    int idx = blockIdx.x * 256 + threadIdx.x;
    if (idx >= NB * H3) return;
    int n = idx / H3, k = idx - n * H3;
    float val;
    if (k < HD)            val = v[(size_t)n * HD + k];
    else if (k < 2 * HD)   val = catv[(size_t)(n / 20) * HD + (k - HD)];
    else                   val = inner[(size_t)n * HD + (k - 2 * HD)];
    fin[idx] = val;
}

// heads (row-major)
__global__ void heads(const float* __restrict__ f, const float* __restrict__ rw,
                      const float* __restrict__ rb, const float* __restrict__ cw,
                      const float* __restrict__ cb, float* __restrict__ out)
{
    int n = blockIdx.x;
    __shared__ float s1[256], s2[256];
    float p1 = 0.f, p2 = 0.f;
    for (int k = threadIdx.x; k < HD; k += 256) {
        float fv = f[(size_t)n * HD + k];
        p1 += fv * rw[k]; p2 += fv * cw[k];
    }
    s1[threadIdx.x] = p1; s2[threadIdx.x] = p2;
    __syncthreads();
    for (int s = 128; s > 0; s >>= 1) {
        if (threadIdx.x < s) { s1[threadIdx.x] += s1[threadIdx.x + s]; s2[threadIdx.x] += s2[threadIdx.x + s]; }
        __syncthreads();
    }
    if (threadIdx.x == 0) {
        out[n]      = s1[0] + rb[0];
        out[NB + n] = fsig(s2[0] + cb[0]);
    }
}

// =================================================================
extern "C" void kernel_launch(void* const* d_in, const int* in_sizes, int n_in,
                              void* d_out, int out_size)
{
    const float* weekly  = (const float*)d_in[0];
    const float* Wih     = (const float*)d_in[1];
    const float* Whh     = (const float*)d_in[2];
    const float* bih     = (const float*)d_in[3];
    const float* bhh     = (const float*)d_in[4];
    const float* encW    = (const float*)d_in[5];
    const float* encB    = (const float*)d_in[6];
    const float* poolW   = (const float*)d_in[7];
    const float* poolB   = (const float*)d_in[8];
    const float* innerW  = (const float*)d_in[9];
    const float* innerAs = (const float*)d_in[10];
    const float* innerAd = (const float*)d_in[11];
    const float* innerB  = (const float*)d_in[12];
    const float* catW    = (const float*)d_in[13];
    const float* catAs   = (const float*)d_in[14];
    const float* catAd   = (const float*)d_in[15];
    const float* catB    = (const float*)d_in[16];
    const float* fusW    = (const float*)d_in[17];
    const float* fusB    = (const float*)d_in[18];
    const float* regW    = (const float*)d_in[19];
    const float* regB    = (const float*)d_in[20];
    const float* clsW    = (const float*)d_in[21];
    const float* clsB    = (const float*)d_in[22];
    float* out = (float*)d_out;

    float *xp, *hbt, *v, *hp, *inner, *catv, *hp2, *catg, *as_, *ad_, *as2, *ad2, *fin, *f;
    unsigned* hfragu;
    cudaGetSymbolAddress((void**)&xp,     g_xp);
    cudaGetSymbolAddress((void**)&hbt,    g_hbt);
    cudaGetSymbolAddress((void**)&hfragu, g_hfrag);
    cudaGetSymbolAddress((void**)&v,      g_v);
    cudaGetSymbolAddress((void**)&hp,     g_hp);
    cudaGetSymbolAddress((void**)&inner,  g_inner);
    cudaGetSymbolAddress((void**)&catv,   g_catv);
    cudaGetSymbolAddress((void**)&hp2,    g_hp2);
    cudaGetSymbolAddress((void**)&catg,   g_cat);
    cudaGetSymbolAddress((void**)&as_,    g_as);
    cudaGetSymbolAddress((void**)&ad_,    g_ad);
    cudaGetSymbolAddress((void**)&as2,    g_as2);
    cudaGetSymbolAddress((void**)&ad2,    g_ad2);
    cudaGetSymbolAddress((void**)&fin,    g_fin);
    cudaGetSymbolAddress((void**)&f,      g_f);

    // 1) xp = weekly @ Wih^T + bih, written as [t][b][g] (remap=1)
    gemm_nt_tc<<<dim3(H3 / 128, (NB * TT) / 128), 256>>>(weekly, Wih, bih, xp, NB * TT, H3, IND, 0, 1);

    // 2) persistent fp16 mma GRU
    cudaFuncSetAttribute(gru_mma, cudaFuncAttributeMaxDynamicSharedMemorySize, GRU_SMEM);
    gru_mma<<<128, 256, GRU_SMEM>>>(xp, Whh, bhh, hbt, hfragu);

    // 3) S(512 x 102400) = encW @ Hflat + encB[u]
    gemm_nn_tc<<<dim3(NDB / 128, TT / 128), 256>>>(encW, hbt, encB, xp, TT, NDB, TT, (size_t)HBT_STRIDE);

    // 4) v[j] = softmax-over-u(S) . H
    att_reduce_flat<<<NDB / 256, 256>>>(xp, hbt, v);

    // 5) inner GAT: hp = v @ innerW^T
    gemm_nt<<<dim3(HD / 128, 1), 256>>>(v, innerW, nullptr, hp, NB, HD, HD, 0);
    dot2<<<NB, 256>>>(hp, innerAs, innerAd, as_, ad_);
    gat_agg<<<NB, 256>>>(hp, as_, ad_, innerB, inner, 20);

    // 6) pool 20 stocks -> category vectors
    pool_att<<<dim3(5, HD / 256), 256>>>(v, poolW, poolB, catv);

    // 7) category GAT
    gemm_nt<<<dim3(HD / 128, 1), 256>>>(catv, catW, nullptr, hp2, 5, HD, HD, 0);
    dot2<<<5, 256>>>(hp2, catAs, catAd, as2, ad2);
    gat_agg<<<5, 256>>>(hp2, as2, ad2, catB, catg, 5);

    // 8) fusion
    build_fusion<<<(NB * H3 + 255) / 256, 256>>>(v, catg, inner, fin);
    gemm_nt<<<dim3(HD / 128, 1), 256>>>(fin, fusW, fusB, f, NB, HD, H3, 1);

    // 9) heads
    heads<<<NB, 256>>>(f, regW, regB, clsW, clsB, out);
}

// round 16
// speedup vs baseline: 1.3778x; 1.3778x over previous
#include <cuda_runtime.h>
#include <cuda_fp16.h>
#include <math.h>
#include <stdint.h>
#include <stddef.h>

typedef unsigned long long u64;

#define NB   100
#define TT   512
#define IND  256
#define HD   1024
#define H3   3072
#define NDB  (HD * NB)          // 102400
#define HBT_STRIDE (128 * 1024) // padded per-t stride (128 batch rows x 1024)
#define HFRAGU_T 28672          // uint32 per t in fp16 fragment layout (8*7*8*32*4)

// ---------------- scratch ----------------
__device__ float    g_xp [(size_t)TT * NB * H3];    // xp [t][b][g]; later reused as S [u][j]
__device__ float    g_hbt[(size_t)TT * HBT_STRIDE]; // h states [t][b(pad128)][k] fp32
__device__ unsigned g_hfrag[(size_t)TT * HFRAGU_T]; // h states, fp16 mma A-fragment layout
__device__ float g_v  [NB * HD];
__device__ float g_hp [NB * HD];
__device__ float g_inner[NB * HD];
__device__ float g_catv[5 * HD];
__device__ float g_hp2 [5 * HD];
__device__ float g_cat [5 * HD];
__device__ float g_as[NB];
__device__ float g_ad[NB];
__device__ float g_as2[8];
__device__ float g_ad2[8];
__device__ float g_fin[NB * H3];
__device__ float g_f  [NB * HD];
__device__ unsigned g_cnt;
__device__ unsigned g_gen;

// ---------------- helpers ----------------
__device__ __forceinline__ u64 bcast2(float x) {
    u64 r; unsigned u = __float_as_uint(x);
    asm("mov.b64 %0, {%1, %1};" : "=l"(r) : "r"(u));
    return r;
}
__device__ __forceinline__ void fma2(u64& d, u64 a, u64 b) {
    asm("fma.rn.f32x2 %0, %1, %2, %0;" : "+l"(d) : "l"(a), "l"(b));
}
__device__ __forceinline__ float2 unpk(u64 v) {
    unsigned lo, hi;
    asm("mov.b64 {%0, %1}, %2;" : "=r"(lo), "=r"(hi) : "l"(v));
    return make_float2(__uint_as_float(lo), __uint_as_float(hi));
}
__device__ __forceinline__ uint32_t f2tf32(float x) {
    uint32_t u;
    asm("cvt.rna.tf32.f32 %0, %1;" : "=r"(u) : "f"(x));
    return u;
}
__device__ __forceinline__ uint32_t packh2(float lo, float hi) {
    __half2 h = __floats2half2_rn(lo, hi);
    return *(uint32_t*)&h;
}
__device__ __forceinline__ float fsig(float x) {
    return __fdividef(1.f, 1.f + __expf(-x));
}
__device__ __forceinline__ float ftanh(float x) {
    float ax = fabsf(x);
    float e = __expf(2.f * ax);
    float t = 1.f - __fdividef(2.f, e + 1.f);
    return copysignf(t, x);
}

// tf32 warp MMA: D(16x8) += A(16x8) * B(8x8)
__device__ __forceinline__ void mma_tf32(
    float& c0, float& c1, float& c2, float& c3,
    uint32_t a0, uint32_t a1, uint32_t a2, uint32_t a3,
    uint32_t b0, uint32_t b1)
{
    asm volatile(
        "mma.sync.aligned.m16n8k8.row.col.f32.tf32.tf32.f32 "
        "{%0,%1,%2,%3}, {%4,%5,%6,%7}, {%8,%9}, {%0,%1,%2,%3};"
        : "+f"(c0), "+f"(c1), "+f"(c2), "+f"(c3)
        : "r"(a0), "r"(a1), "r"(a2), "r"(a3), "r"(b0), "r"(b1));
}
// fp16 warp MMA: D(16x8) += A(16x16) * B(16x8), fp32 accumulate
__device__ __forceinline__ void mma_f16(
    float& c0, float& c1, float& c2, float& c3,
    uint32_t a0, uint32_t a1, uint32_t a2, uint32_t a3,
    uint32_t b0, uint32_t b1)
{
    asm volatile(
        "mma.sync.aligned.m16n8k16.row.col.f32.f16.f16.f32 "
        "{%0,%1,%2,%3}, {%4,%5,%6,%7}, {%8,%9}, {%0,%1,%2,%3};"
        : "+f"(c0), "+f"(c1), "+f"(c2), "+f"(c3)
        : "r"(a0), "r"(a1), "r"(a2), "r"(a3), "r"(b0), "r"(b1));
}

// =================================================================
// tf32 tensor-core GEMM NT (remap: xp stored as [t][b][g])
// =================================================================
#define AST 36
__global__ __launch_bounds__(256) void gemm_nt_tc(
    const float* __restrict__ A, const float* __restrict__ B,
    const float* __restrict__ colbias, float* __restrict__ C,
    int M, int N, int K, int act, int remap)
{
    __shared__ uint32_t As[128 * AST];
    __shared__ uint32_t Bs[128 * AST];
    int tid = threadIdx.x, w = tid >> 5, lane = tid & 31;
    int gid = lane >> 2, tig = lane & 3;
    int wm = w >> 2, wn = w & 3;
    int row0 = blockIdx.y * 128, col0 = blockIdx.x * 128;

    float acc[4][4][4];
#pragma unroll
    for (int i = 0; i < 4; i++)
#pragma unroll
        for (int j = 0; j < 4; j++)
#pragma unroll
            for (int q = 0; q < 4; q++) acc[i][j][q] = 0.f;

    for (int k0 = 0; k0 < K; k0 += 32) {
#pragma unroll
        for (int q = 0; q < 4; q++) {
            int idx = tid + q * 256;
            int row = idx >> 3, k4 = (idx & 7) * 4;
            float4 v = *(const float4*)(A + (size_t)(row0 + row) * K + k0 + k4);
            uint32_t* d = &As[row * AST + k4];
            d[0] = f2tf32(v.x); d[1] = f2tf32(v.y); d[2] = f2tf32(v.z); d[3] = f2tf32(v.w);
        }
#pragma unroll
        for (int q = 0; q < 4; q++) {
            int idx = tid + q * 256;
            int row = idx >> 3, k4 = (idx & 7) * 4;
            float4 v = *(const float4*)(B + (size_t)(col0 + row) * K + k0 + k4);
            uint32_t* d = &Bs[row * AST + k4];
            d[0] = f2tf32(v.x); d[1] = f2tf32(v.y); d[2] = f2tf32(v.z); d[3] = f2tf32(v.w);
        }
        __syncthreads();
#pragma unroll
        for (int kq = 0; kq < 4; kq++) {
            int kb = kq * 8;
            uint32_t af[4][4];
#pragma unroll
            for (int i = 0; i < 4; i++) {
                int base = (wm * 64 + i * 16 + gid) * AST + kb + tig;
                af[i][0] = As[base];
                af[i][1] = As[base + 8 * AST];
                af[i][2] = As[base + 4];
                af[i][3] = As[base + 8 * AST + 4];
            }
#pragma unroll
            for (int j = 0; j < 4; j++) {
                int bbase = (wn * 32 + j * 8 + gid) * AST + kb + tig;
                uint32_t b0 = Bs[bbase], b1 = Bs[bbase + 4];
#pragma unroll
                for (int i = 0; i < 4; i++)
                    mma_tf32(acc[i][j][0], acc[i][j][1], acc[i][j][2], acc[i][j][3],
                             af[i][0], af[i][1], af[i][2], af[i][3], b0, b1);
            }
        }
        __syncthreads();
    }
#pragma unroll
    for (int i = 0; i < 4; i++) {
#pragma unroll
        for (int j = 0; j < 4; j++) {
            int r = row0 + wm * 64 + i * 16 + gid;
            int r2 = r + 8;
            int cix = col0 + wn * 32 + j * 8 + tig * 2;
            float v0 = acc[i][j][0], v1 = acc[i][j][1];
            float v2 = acc[i][j][2], v3 = acc[i][j][3];
            if (colbias) {
                float bb0 = colbias[cix], bb1 = colbias[cix + 1];
                v0 += bb0; v1 += bb1; v2 += bb0; v3 += bb1;
            }
            if (act == 1) {
                v0 = fmaxf(v0, 0.f); v1 = fmaxf(v1, 0.f);
                v2 = fmaxf(v2, 0.f); v3 = fmaxf(v3, 0.f);
            }
            size_t ro = (size_t)r, ro2 = (size_t)r2;
            if (remap) {
                ro  = (size_t)(r  % TT) * NB + (r  / TT);
                ro2 = (size_t)(r2 % TT) * NB + (r2 / TT);
            }
            C[ro  * N + cix]     = v0;
            C[ro  * N + cix + 1] = v1;
            C[ro2 * N + cix]     = v2;
            C[ro2 * N + cix + 1] = v3;
        }
    }
}

// =================================================================
// tf32 tensor-core GEMM NN: C[M,N] = A[M,K] @ B[K(ldB),N] + rowbias[M]
// =================================================================
#define BSTN 132
__global__ __launch_bounds__(256) void gemm_nn_tc(
    const float* __restrict__ A, const float* __restrict__ B,
    const float* __restrict__ rowbias, float* __restrict__ C,
    int M, int N, int K, size_t ldB)
{
    __shared__ uint32_t As[128 * AST];
    __shared__ uint32_t Bs[32 * BSTN];
    int tid = threadIdx.x, w = tid >> 5, lane = tid & 31;
    int gid = lane >> 2, tig = lane & 3;
    int wm = w >> 2, wn = w & 3;
    int row0 = blockIdx.y * 128, col0 = blockIdx.x * 128;

    float acc[4][4][4];
#pragma unroll
    for (int i = 0; i < 4; i++)
#pragma unroll
        for (int j = 0; j < 4; j++)
#pragma unroll
            for (int q = 0; q < 4; q++) acc[i][j][q] = 0.f;

    for (int k0 = 0; k0 < K; k0 += 32) {
#pragma unroll
        for (int q = 0; q < 4; q++) {
            int idx = tid + q * 256;
            int row = idx >> 3, k4 = (idx & 7) * 4;
            float4 v = *(const float4*)(A + (size_t)(row0 + row) * K + k0 + k4);
            uint32_t* d = &As[row * AST + k4];
            d[0] = f2tf32(v.x); d[1] = f2tf32(v.y); d[2] = f2tf32(v.z); d[3] = f2tf32(v.w);
        }
#pragma unroll
        for (int q = 0; q < 4; q++) {
            int idx = tid + q * 256;
            int k = idx >> 5, n4 = (idx & 31) * 4;
            float4 v = *(const float4*)(B + (size_t)(k0 + k) * ldB + col0 + n4);
            uint32_t* d = &Bs[k * BSTN + n4];
            d[0] = f2tf32(v.x); d[1] = f2tf32(v.y); d[2] = f2tf32(v.z); d[3] = f2tf32(v.w);
        }
        __syncthreads();
#pragma unroll
        for (int kq = 0; kq < 4; kq++) {
            int kb = kq * 8;
            uint32_t af[4][4];
#pragma unroll
            for (int i = 0; i < 4; i++) {
                int base = (wm * 64 + i * 16 + gid) * AST + kb + tig;
                af[i][0] = As[base];
                af[i][1] = As[base + 8 * AST];
                af[i][2] = As[base + 4];
                af[i][3] = As[base + 8 * AST + 4];
            }
#pragma unroll
            for (int j = 0; j < 4; j++) {
                int ncol = wn * 32 + j * 8 + gid;
                uint32_t b0 = Bs[(kb + tig) * BSTN + ncol];
                uint32_t b1 = Bs[(kb + tig + 4) * BSTN + ncol];
#pragma unroll
                for (int i = 0; i < 4; i++)
                    mma_tf32(acc[i][j][0], acc[i][j][1], acc[i][j][2], acc[i][j][3],
                             af[i][0], af[i][1], af[i][2], af[i][3], b0, b1);
            }
        }
        __syncthreads();
    }
#pragma unroll
    for (int i = 0; i < 4; i++) {
#pragma unroll
        for (int j = 0; j < 4; j++) {
            int r = row0 + wm * 64 + i * 16 + gid;
            int cix = col0 + wn * 32 + j * 8 + tig * 2;
            float rb0 = rowbias ? rowbias[r] : 0.f;
            float rb8 = rowbias ? rowbias[r + 8] : 0.f;
            C[(size_t)r * N + cix]           = acc[i][j][0] + rb0;
            C[(size_t)r * N + cix + 1]       = acc[i][j][1] + rb0;
            C[(size_t)(r + 8) * N + cix]     = acc[i][j][2] + rb8;
            C[(size_t)(r + 8) * N + cix + 1] = acc[i][j][3] + rb8;
        }
    }
}

// =================================================================
// SIMT SGEMM NT (small GEMMs)
// =================================================================
__global__ __launch_bounds__(256) void gemm_nt(
    const float* __restrict__ A, const float* __restrict__ B,
    const float* __restrict__ colbias, float* __restrict__ C,
    int M, int N, int K, int act)
{
    __shared__ float As[16][128];
    __shared__ float Bs[16][128];
    int tid = threadIdx.x;
    int tx = tid & 15, ty = tid >> 4;
    int row0 = blockIdx.y * 128, col0 = blockIdx.x * 128;

    u64 acc[8][4];
#pragma unroll
    for (int i = 0; i < 8; i++)
#pragma unroll
        for (int j = 0; j < 4; j++) acc[i][j] = 0ull;

    int lr = tid >> 2, lc = tid & 3;
    for (int k0 = 0; k0 < K; k0 += 16) {
#pragma unroll
        for (int p = 0; p < 2; p++) {
            int r = lr + p * 64, gr = row0 + r;
            float4 v = make_float4(0.f, 0.f, 0.f, 0.f);
            if (gr < M) v = *(const float4*)(A + (size_t)gr * K + k0 + lc * 4);
            As[lc*4+0][r] = v.x; As[lc*4+1][r] = v.y; As[lc*4+2][r] = v.z; As[lc*4+3][r] = v.w;
        }
#pragma unroll
        for (int p = 0; p < 2; p++) {
            int r = lr + p * 64, gc = col0 + r;
            float4 v = make_float4(0.f, 0.f, 0.f, 0.f);
            if (gc < N) v = *(const float4*)(B + (size_t)gc * K + k0 + lc * 4);
            Bs[lc*4+0][r] = v.x; Bs[lc*4+1][r] = v.y; Bs[lc*4+2][r] = v.z; Bs[lc*4+3][r] = v.w;
        }
        __syncthreads();
#pragma unroll
        for (int kk = 0; kk < 16; kk++) {
            float a[8];
            *(float4*)&a[0] = *(const float4*)&As[kk][ty * 8];
            *(float4*)&a[4] = *(const float4*)&As[kk][ty * 8 + 4];
            u64 b4[4];
#pragma unroll
            for (int j = 0; j < 4; j++) b4[j] = *(const u64*)&Bs[kk][tx * 8 + 2 * j];
#pragma unroll
            for (int i = 0; i < 8; i++) {
                u64 ai = bcast2(a[i]);
#pragma unroll
                for (int j = 0; j < 4; j++) fma2(acc[i][j], ai, b4[j]);
            }
        }
        __syncthreads();
    }
#pragma unroll
    for (int i = 0; i < 8; i++) {
        int gm = row0 + ty * 8 + i;
        if (gm >= M) continue;
#pragma unroll
        for (int j = 0; j < 4; j++) {
            float2 c2 = unpk(acc[i][j]);
            int gn = col0 + tx * 8 + 2 * j;
            float v0 = c2.x, v1 = c2.y;
            if (colbias) { v0 += colbias[gn]; v1 += colbias[gn + 1]; }
            if (act == 1) { v0 = fmaxf(v0, 0.f); v1 = fmaxf(v1, 0.f); }
            if (gn < N)     C[(size_t)gm * N + gn]     = v0;
            if (gn + 1 < N) C[(size_t)gm * N + gn + 1] = v1;
        }
    }
}

// =================================================================
// Persistent GRU v16 = R14 + register-resident hold ONLY.
// fp16 mma.m16n8k16, A operands direct from fp16 fragment hfrag.
// 128 blocks x 256 threads (8 warps). Block owns 8 hidden cols.
// =================================================================
#define PBS 9
#define PBUF_F (112 * 24 * PBS)
#define GRU_SMEM (PBUF_F * 4)

__device__ __forceinline__ void gridbar()
{
    __threadfence();
    __syncthreads();
    if (threadIdx.x == 0) {
        volatile unsigned* vg = &g_gen;
        unsigned target = *vg + 1;
        if (atomicAdd(&g_cnt, 1) == gridDim.x - 1) {
            g_cnt = 0;
            __threadfence();
            atomicAdd(&g_gen, 1);
        } else {
            while ((int)(*vg - target) < 0) { }
        }
        __threadfence();
    }
    __syncthreads();
}

__global__ __launch_bounds__(256, 1) void gru_mma(
    const float* __restrict__ xpt, const float* __restrict__ Whh,
    const float* __restrict__ bhh, float* __restrict__ hbt,
    unsigned* __restrict__ hfragu)
{
    extern __shared__ float pbuf[];
    int tid  = threadIdx.x;
    int w    = tid >> 5;
    int lane = tid & 31;
    int gidq = lane >> 2;
    int tig  = lane & 3;
    int col0 = blockIdx.x * 8;
    int k0   = w * 128;

    // register-resident Whh fragments (fp16, 48 regs)
    uint32_t bf[8][3][2];
#pragma unroll
    for (int kt = 0; kt < 8; kt++) {
#pragma unroll
        for (int j = 0; j < 3; j++) {
            int n = j * 8 + gidq;
            int c = n / 3, g = n % 3;
            const float* wrow = Whh + ((size_t)g * HD + col0 + c) * HD;
            int kb = k0 + kt * 16 + 2 * tig;
            bf[kt][j][0] = packh2(wrow[kb],     wrow[kb + 1]);
            bf[kt][j][1] = packh2(wrow[kb + 8], wrow[kb + 9]);
        }
    }

    float holdr[4] = { 0.f, 0.f, 0.f, 0.f };   // h(t-1) for this thread's 4 (b,col) pairs

    for (int t = 0; t < TT; t++) {
        if (t > 0) {
            const uint4* fb = (const uint4*)(hfragu + (size_t)(t - 1) * HFRAGU_T)
                              + (size_t)w * 7 * 8 * 32 + lane;
#pragma unroll 1
            for (int mt = 0; mt < 7; mt++) {
                float c0[3], c1[3], c2[3], c3[3];
#pragma unroll
                for (int j = 0; j < 3; j++) { c0[j] = 0.f; c1[j] = 0.f; c2[j] = 0.f; c3[j] = 0.f; }

                const uint4* fm = fb + (size_t)(mt * 8) * 32;
#pragma unroll
                for (int kt = 0; kt < 8; kt++) {
                    uint4 a = fm[(size_t)kt * 32];
#pragma unroll
                    for (int j = 0; j < 3; j++)
                        mma_f16(c0[j], c1[j], c2[j], c3[j],
                                a.x, a.y, a.z, a.w, bf[kt][j][0], bf[kt][j][1]);
                }

                int r0 = mt * 16 + gidq;
#pragma unroll
                for (int j = 0; j < 3; j++) {
                    int n0 = j * 8 + tig * 2;
                    pbuf[((size_t)r0 * 24 + n0) * PBS + w]           = c0[j];
                    pbuf[((size_t)r0 * 24 + n0 + 1) * PBS + w]       = c1[j];
                    pbuf[((size_t)(r0 + 8) * 24 + n0) * PBS + w]     = c2[j];
                    pbuf[((size_t)(r0 + 8) * 24 + n0 + 1) * PBS + w] = c3[j];
                }
            }
        }
        __syncthreads();

        // fused reduction + gate epilogue (static idx->(b,c); hold in regs)
        __half* hf = (__half*)(hfragu + (size_t)t * HFRAGU_T);
#pragma unroll
        for (int q = 0; q < 4; q++) {
            int idx = tid + q * 256;
            if (idx < NB * 8) {
                int b = idx >> 3, c = idx & 7;
                int col = col0 + c;
                float ar = 0.f, az = 0.f, an = 0.f;
                if (t > 0) {
                    const float* pr = pbuf + ((size_t)b * 24 + c * 3) * PBS;
#pragma unroll
                    for (int ww = 0; ww < 8; ww++) {
                        ar += pr[ww];
                        az += pr[PBS + ww];
                        an += pr[2 * PBS + ww];
                    }
                }
                size_t xbase = ((size_t)t * NB + b) * H3;
                float xr = xpt[xbase + col];
                float xz = xpt[xbase + HD + col];
                float xn = xpt[xbase + 2 * HD + col];
                float r = fsig(xr + ar + bhh[col]);
                float z = fsig(xz + az + bhh[HD + col]);
                float n = ftanh(xn + r * (an + bhh[2 * HD + col]));
                float hnew = (1.f - z) * n + z * holdr[q];
                holdr[q] = hnew;

                hbt[(size_t)t * HBT_STRIDE + (size_t)b * HD + col] = hnew;

                // fp16 fragment-layout write
                int fw  = col >> 7;
                int kl  = col & 127;
                int fkt = kl >> 4;
                int kk  = kl & 15;
                int ah  = kk >> 3;
                int ktg = (kk & 7) >> 1;
                int hlf = kk & 1;
                int fgid = b & 7;
                int rh   = (b >> 3) & 1;
                int fmt  = b >> 4;
                size_t u32idx = ((((size_t)fw * 7 + fmt) * 8 + fkt) * 32 + fgid * 4 + ktg) * 4
                                + (rh + 2 * ah);
                hf[u32idx * 2 + hlf] = __float2half_rn(hnew);
            }
        }

        gridbar();
    }
}

// =================================================================
// one-pass online-softmax reduce
// =================================================================
__global__ void att_reduce_flat(const float* __restrict__ S,
                                const float* __restrict__ H,
                                float* __restrict__ v)
{
    int j = blockIdx.x * 256 + threadIdx.x;
    float mx = -1e30f, se = 0.f, sv = 0.f;
#pragma unroll 4
    for (int u = 0; u < TT; u++) {
        float s = S[(size_t)u * NDB + j];
        float h = H[(size_t)u * HBT_STRIDE + j];
        float m2 = fmaxf(mx, s);
        float cor = __expf(mx - m2);
        float e = __expf(s - m2);
        se = se * cor + e;
        sv = sv * cor + e * h;
        mx = m2;
    }
    v[j] = __fdividef(sv, se);
}

// pool attention, row-major v -> catv[c][d]
__global__ void pool_att(const float* __restrict__ v, const float* __restrict__ pW,
                         const float* __restrict__ pb, float* __restrict__ catv)
{
    int c = blockIdx.x;
    int d = blockIdx.y * 256 + threadIdx.x;
    __shared__ float sW[400];
    __shared__ float sb[20];
    for (int i = threadIdx.x; i < 400; i += 256) sW[i] = pW[i];
    if (threadIdx.x < 20) sb[threadIdx.x] = pb[threadIdx.x];
    __syncthreads();

    float xv[20];
#pragma unroll
    for (int s = 0; s < 20; s++) xv[s] = v[(size_t)(c * 20 + s) * HD + d];
    float wv[20]; float mx = -1e30f;
#pragma unroll
    for (int u = 0; u < 20; u++) {
        float s = sb[u];
#pragma unroll
        for (int t2 = 0; t2 < 20; t2++) s += xv[t2] * sW[u * 20 + t2];
        wv[u] = s; mx = fmaxf(mx, s);
    }
    float se = 0.f, sv = 0.f;
#pragma unroll
    for (int u = 0; u < 20; u++) {
        float e = __expf(wv[u] - mx);
        se += e; sv += e * xv[u];
    }
    catv[(size_t)c * HD + d] = __fdividef(sv, se);
}

// two dots per node (row-major)
__global__ void dot2(const float* __restrict__ h, const float* __restrict__ a1,
                     const float* __restrict__ a2, float* __restrict__ o1,
                     float* __restrict__ o2)
{
    int n = blockIdx.x;
    __shared__ float s1[256], s2[256];
    float p1 = 0.f, p2 = 0.f;
    for (int k = threadIdx.x; k < HD; k += 256) {
        float hv = h[(size_t)n * HD + k];
        p1 += hv * a1[k]; p2 += hv * a2[k];
    }
    s1[threadIdx.x] = p1; s2[threadIdx.x] = p2;
    __syncthreads();
    for (int s = 128; s > 0; s >>= 1) {
        if (threadIdx.x < s) { s1[threadIdx.x] += s1[threadIdx.x + s]; s2[threadIdx.x] += s2[threadIdx.x + s]; }
        __syncthreads();
    }
    if (threadIdx.x == 0) { o1[n] = s1[0]; o2[n] = s2[0]; }
}

// GAT aggregation (complete cliques + self loops), row-major
__global__ void gat_agg(const float* __restrict__ h, const float* __restrict__ as,
                        const float* __restrict__ ad, const float* __restrict__ bias,
                        float* __restrict__ out, int group)
{
    int n = blockIdx.x;
    int base = (n / group) * group;
    __shared__ float alpha[32];
    if (threadIdx.x == 0) {
        float e[32]; float mx = -1e30f;
        for (int s = 0; s < group; s++) {
            float x = as[base + s] + ad[n];
            x = (x > 0.f) ? x : 0.2f * x;
            e[s] = x; mx = fmaxf(mx, x);
        }
        float se = 0.f;
        for (int s = 0; s < group; s++) { e[s] = __expf(e[s] - mx); se += e[s]; }
        for (int s = 0; s < group; s++) alpha[s] = __fdividef(e[s], se);
    }
    __syncthreads();
    for (int dd = threadIdx.x; dd < HD; dd += 256) {
        float acc = 0.f;
        for (int s = 0; s < group; s++)
            acc += alpha[s] * h[(size_t)(base + s) * HD + dd];
        out[(size_t)n * HD + dd] = acc + bias[dd];
    }
}

// fusion concat (row-major)
__global__ void build_fusion(const float* __restrict__ v, const float* __restrict__ catv,
                             const float* __restrict__ inner, float* __restrict__ fin)
{
    int idx = blockIdx.x * 256 + threadIdx.x;
    if (idx >= NB * H3) return;
    int n = idx / H3, k = idx - n * H3;
    float val;
    if (k < HD)            val = v[(size_t)n * HD + k];
    else if (k < 2 * HD)   val = catv[(size_t)(n / 20) * HD + (k - HD)];
    else                   val = inner[(size_t)n * HD + (k - 2 * HD)];
    fin[idx] = val;
}

// heads (row-major)
__global__ void heads(const float* __restrict__ f, const float* __restrict__ rw,
                      const float* __restrict__ rb, const float* __restrict__ cw,
                      const float* __restrict__ cb, float* __restrict__ out)
{
    int n = blockIdx.x;
    __shared__ float s1[256], s2[256];
    float p1 = 0.f, p2 = 0.f;
    for (int k = threadIdx.x; k < HD; k += 256) {
        float fv = f[(size_t)n * HD + k];
        p1 += fv * rw[k]; p2 += fv * cw[k];
    }
    s1[threadIdx.x] = p1; s2[threadIdx.x] = p2;
    __syncthreads();
    for (int s = 128; s > 0; s >>= 1) {
        if (threadIdx.x < s) { s1[threadIdx.x] += s1[threadIdx.x + s]; s2[threadIdx.x] += s2[threadIdx.x + s]; }
        __syncthreads();
    }
    if (threadIdx.x == 0) {
        out[n]      = s1[0] + rb[0];
        out[NB + n] = fsig(s2[0] + cb[0]);
    }
}

// =================================================================
extern "C" void kernel_launch(void* const* d_in, const int* in_sizes, int n_in,
                              void* d_out, int out_size)
{
    const float* weekly  = (const float*)d_in[0];
    const float* Wih     = (const float*)d_in[1];
    const float* Whh     = (const float*)d_in[2];
    const float* bih     = (const float*)d_in[3];
    const float* bhh     = (const float*)d_in[4];
    const float* encW    = (const float*)d_in[5];
    const float* encB    = (const float*)d_in[6];
    const float* poolW   = (const float*)d_in[7];
    const float* poolB   = (const float*)d_in[8];
    const float* innerW  = (const float*)d_in[9];
    const float* innerAs = (const float*)d_in[10];
    const float* innerAd = (const float*)d_in[11];
    const float* innerB  = (const float*)d_in[12];
    const float* catW    = (const float*)d_in[13];
    const float* catAs   = (const float*)d_in[14];
    const float* catAd   = (const float*)d_in[15];
    const float* catB    = (const float*)d_in[16];
    const float* fusW    = (const float*)d_in[17];
    const float* fusB    = (const float*)d_in[18];
    const float* regW    = (const float*)d_in[19];
    const float* regB    = (const float*)d_in[20];
    const float* clsW    = (const float*)d_in[21];
    const float* clsB    = (const float*)d_in[22];
    float* out = (float*)d_out;

    float *xp, *hbt, *v, *hp, *inner, *catv, *hp2, *catg, *as_, *ad_, *as2, *ad2, *fin, *f;
    unsigned* hfragu;
    cudaGetSymbolAddress((void**)&xp,     g_xp);
    cudaGetSymbolAddress((void**)&hbt,    g_hbt);
    cudaGetSymbolAddress((void**)&hfragu, g_hfrag);
    cudaGetSymbolAddress((void**)&v,      g_v);
    cudaGetSymbolAddress((void**)&hp,     g_hp);
    cudaGetSymbolAddress((void**)&inner,  g_inner);
    cudaGetSymbolAddress((void**)&catv,   g_catv);
    cudaGetSymbolAddress((void**)&hp2,    g_hp2);
    cudaGetSymbolAddress((void**)&catg,   g_cat);
    cudaGetSymbolAddress((void**)&as_,    g_as);
    cudaGetSymbolAddress((void**)&ad_,    g_ad);
    cudaGetSymbolAddress((void**)&as2,    g_as2);
    cudaGetSymbolAddress((void**)&ad2,    g_ad2);
    cudaGetSymbolAddress((void**)&fin,    g_fin);
    cudaGetSymbolAddress((void**)&f,      g_f);

    // 1) xp = weekly @ Wih^T + bih, written as [t][b][g] (remap=1)
    gemm_nt_tc<<<dim3(H3 / 128, (NB * TT) / 128), 256>>>(weekly, Wih, bih, xp, NB * TT, H3, IND, 0, 1);

    // 2) persistent fp16 mma GRU
    cudaFuncSetAttribute(gru_mma, cudaFuncAttributeMaxDynamicSharedMemorySize, GRU_SMEM);
    gru_mma<<<128, 256, GRU_SMEM>>>(xp, Whh, bhh, hbt, hfragu);

    // 3) S(512 x 102400) = encW @ Hflat + encB[u]
    gemm_nn_tc<<<dim3(NDB / 128, TT / 128), 256>>>(encW, hbt, encB, xp, TT, NDB, TT, (size_t)HBT_STRIDE);

    // 4) v[j] = softmax-over-u(S) . H
    att_reduce_flat<<<NDB / 256, 256>>>(xp, hbt, v);

    // 5) inner GAT: hp = v @ innerW^T
    gemm_nt<<<dim3(HD / 128, 1), 256>>>(v, innerW, nullptr, hp, NB, HD, HD, 0);
    dot2<<<NB, 256>>>(hp, innerAs, innerAd, as_, ad_);
    gat_agg<<<NB, 256>>>(hp, as_, ad_, innerB, inner, 20);

    // 6) pool 20 stocks -> category vectors
    pool_att<<<dim3(5, HD / 256), 256>>>(v, poolW, poolB, catv);

    // 7) category GAT
    gemm_nt<<<dim3(HD / 128, 1), 256>>>(catv, catW, nullptr, hp2, 5, HD, HD, 0);
    dot2<<<5, 256>>>(hp2, catAs, catAd, as2, ad2);
    gat_agg<<<5, 256>>>(hp2, as2, ad2, catB, catg, 5);

    // 8) fusion
    build_fusion<<<(NB * H3 + 255) / 256, 256>>>(v, catg, inner, fin);
    gemm_nt<<<dim3(HD / 128, 1), 256>>>(fin, fusW, fusB, f, NB, HD, H3, 1);

    // 9) heads
    heads<<<NB, 256>>>(f, regW, regB, clsW, clsB, out);
}